// round 13
// baseline (speedup 1.0000x reference)
#include <cuda_runtime.h>
#include <cuda_fp16.h>
#include <cstdint>

// ---------------- problem constants ----------------
constexpr int Nn   = 50000;          // nodes
constexpr int Ee   = 800000;         // edges (w/o self loops)
constexpr int ET   = Ee + Nn;        // edges incl. self loops
constexpr int IND  = 128;            // input dim
constexpr int C0   = 128;            // layer0 out channels (2 heads * 64)
constexpr int OUTD = 64;             // layer1 out channels (1 head)
constexpr float NEG_SLOPE = 0.2f;
constexpr float BN_EPS    = 1e-5f;

constexpr int SCAN_B = 1024;
constexpr int NB1    = (Nn + SCAN_B - 1) / SCAN_B;   // 49
constexpr int BN_BLOCKS = 512;

constexpr int ROWW = 264;            // smem words per row (264 mod 32 == 8 -> conflict-free)
constexpr int GEMM_SMEM = 64 * ROWW * 4;   // 67584 bytes

// ---------------- device scratch ----------------
__device__ uint2  g_h0[Nn * 32];         // x@W0 in fp16: 128ch * 2B = 256B/row (12.8 MB)
__device__ float4 g_x1[Nn * C0 / 4];     // layer0 out (pre-BN), fp32
__device__ uint2  g_h1[Nn * 16];         // x1@W1 in fp16: 64ch * 2B = 128B/row (6.4 MB)
__device__ float  g_a0s[Nn * 2];
__device__ float  g_a0d[Nn * 2];
__device__ float  g_a1s[Nn];
__device__ float  g_a1d[Nn];
__device__ float  g_bps[BN_BLOCKS * C0];
__device__ float  g_bpq[BN_BLOCKS * C0];
__device__ float4 g_bnscale[C0 / 4];
__device__ float4 g_bnshift[C0 / 4];
__device__ uint4  g_w0pack[128 * 16 * 4];    // [c][kt][lr] {hi0,hi1,lo0,lo1}
__device__ uint4  g_w1pack[64 * 16 * 4];
// CSR
__device__ int    g_deg   [Nn];
__device__ int    g_cnt   [Nn];
__device__ int    g_incl  [Nn];
__device__ int    g_rowptr[Nn + 1];
__device__ int    g_adj   [ET];
__device__ int    g_bsum  [NB1];

__device__ __forceinline__ float lrelu(float e) {
    return e > 0.f ? e : NEG_SLOPE * e;
}

__device__ __forceinline__ uint32_t f2tf32(float f) {
    uint32_t u;
    asm("cvt.rna.tf32.f32 %0, %1;" : "=r"(u) : "f"(f));
    return u;
}

__device__ __forceinline__ void mma_tf32(float4& c, const uint32_t* a, const uint32_t* b) {
    asm volatile(
        "mma.sync.aligned.m16n8k8.row.col.f32.tf32.tf32.f32 "
        "{%0,%1,%2,%3}, {%4,%5,%6,%7}, {%8,%9}, {%0,%1,%2,%3};"
        : "+f"(c.x), "+f"(c.y), "+f"(c.z), "+f"(c.w)
        : "r"(a[0]), "r"(a[1]), "r"(a[2]), "r"(a[3]), "r"(b[0]), "r"(b[1]));
}

// ---------------- zero both CSR counter arrays in one launch ----------------
__global__ void zero2_kernel(int* p0, int* p1, int n) {
    int i = blockIdx.x * blockDim.x + threadIdx.x;
    for (; i < n; i += gridDim.x * blockDim.x) { p0[i] = 0; p1[i] = 0; }
}

// -------- pre-split W0/W1 into tf32 hi/lo fragment-ordered uint4 ------------
__global__ void wsplit_kernel(const float* __restrict__ W0,
                              const float* __restrict__ W1,
                              uint4* __restrict__ w0p, uint4* __restrict__ w1p) {
    int idx = blockIdx.x * blockDim.x + threadIdx.x;
    if (idx < 128 * 64) {                       // W0: c<128, 16 kt, 4 lr
        int c = idx >> 6, t = idx & 63;
        int kt = t >> 2, lr = t & 3, k0 = 8 * kt;
        float f0 = W0[(k0 + lr) * 128 + c];
        float f1 = W0[(k0 + lr + 4) * 128 + c];
        uint32_t h0 = f2tf32(f0), h1 = f2tf32(f1);
        uint32_t l0 = f2tf32(f0 - __uint_as_float(h0));
        uint32_t l1 = f2tf32(f1 - __uint_as_float(h1));
        w0p[idx] = make_uint4(h0, h1, l0, l1);
    } else if (idx < 128 * 64 + 64 * 64) {      // W1: c<64, 16 kt, 4 lr
        int j = idx - 128 * 64;
        int c = j >> 6, t = j & 63;
        int kt = t >> 2, lr = t & 3, k0 = 8 * kt;
        float f0 = W1[(k0 + lr) * 64 + c];
        float f1 = W1[(k0 + lr + 4) * 64 + c];
        uint32_t h0 = f2tf32(f0), h1 = f2tf32(f1);
        uint32_t l0 = f2tf32(f0 - __uint_as_float(h0));
        uint32_t l1 = f2tf32(f1 - __uint_as_float(h1));
        w1p[c * 64 + kt * 4 + lr] = make_uint4(h0, h1, l0, l1);
    }
}

// ---------------- CSR build ----------------
__global__ void deg_kernel(const int* __restrict__ ei, int* __restrict__ deg) {
    int i = blockIdx.x * blockDim.x + threadIdx.x;
    if (i >= ET) return;
    int dst = (i < Ee) ? ei[Ee + i] : (i - Ee);
    atomicAdd(&deg[dst], 1);
}

__global__ void scan1_kernel(const int* __restrict__ deg,
                             int* __restrict__ incl, int* __restrict__ bsum) {
    __shared__ int wsum[32];
    int tid  = threadIdx.x;
    int lane = tid & 31, wid = tid >> 5;
    int i = blockIdx.x * SCAN_B + tid;
    int v = (i < Nn) ? deg[i] : 0;
#pragma unroll
    for (int off = 1; off < 32; off <<= 1) {
        int t = __shfl_up_sync(0xffffffffu, v, off);
        if (lane >= off) v += t;
    }
    if (lane == 31) wsum[wid] = v;
    __syncthreads();
    if (wid == 0) {
        int w = wsum[lane];
#pragma unroll
        for (int off = 1; off < 32; off <<= 1) {
            int t = __shfl_up_sync(0xffffffffu, w, off);
            if (lane >= off) w += t;
        }
        wsum[lane] = w;
    }
    __syncthreads();
    if (wid > 0) v += wsum[wid - 1];
    if (i < Nn) incl[i] = v;
    if (tid == SCAN_B - 1) bsum[blockIdx.x] = v;
}

__global__ void scan3_kernel(const int* __restrict__ incl,
                             const int* __restrict__ bsum,
                             int* __restrict__ rowptr) {
    __shared__ int bs[NB1];
    for (int k = threadIdx.x; k < NB1; k += blockDim.x) bs[k] = bsum[k];
    __syncthreads();
    int i = blockIdx.x * blockDim.x + threadIdx.x;
    if (i == 0) rowptr[0] = 0;
    if (i >= Nn) return;
    int b = i / SCAN_B;
    int off = 0;
    for (int k = 0; k < b; k++) off += bs[k];
    rowptr[i + 1] = incl[i] + off;
}

__global__ void fill_kernel(const int* __restrict__ ei,
                            const int* __restrict__ rowptr,
                            int* __restrict__ cnt, int* __restrict__ adj) {
    int i = blockIdx.x * blockDim.x + threadIdx.x;
    if (i >= ET) return;
    int src, dst;
    if (i < Ee) { src = ei[i]; dst = ei[Ee + i]; }
    else        { src = dst = i - Ee; }
    int pos = rowptr[dst] + atomicAdd(&cnt[dst], 1);
    adj[pos] = src;
}

// ------ GEMM0 tf32x3: hi/lo-interleaved smem A, pre-split B, fused attdot ---
// 256 threads = 8 warps in 2(m) x 4(n): warp tile m32 x n32, block 64 x 128.
// Output Y stored fp16 (half2) — consumed only by the agg0 gather.
__global__ void gemm0_tf32_att_kernel(const float4* __restrict__ X4,
                                      const uint4* __restrict__ Wp,
                                      __half2* __restrict__ Yh, int nrows,
                                      const float* __restrict__ att_src,
                                      const float* __restrict__ att_dst,
                                      float* __restrict__ a_s,
                                      float* __restrict__ a_d) {
    extern __shared__ uint32_t aw[];                 // [64][ROWW]: {hi,lo} per k
    __shared__ float reds[8][32], redd[8][32];
    const int tid  = threadIdx.x;
    const int lane = tid & 31;
    const int warp = tid >> 5;
    const int warp_m = warp >> 2;
    const int warp_n = warp & 3;
    const int row0 = blockIdx.x * 64;

    // stage X, tf32 hi/lo interleaved: word (r*ROWW + 2k) = hi, +1 = lo
    for (int i = tid; i < 64 * 32; i += 256) {
        int r = i >> 5, kk = i & 31;
        int row = row0 + r;
        float4 v = (row < nrows) ? X4[(size_t)row * 32 + kk]
                                 : make_float4(0.f, 0.f, 0.f, 0.f);
        float f[4] = {v.x, v.y, v.z, v.w};
        uint32_t h[4], l[4];
#pragma unroll
        for (int j = 0; j < 4; j++) {
            h[j] = f2tf32(f[j]);
            l[j] = f2tf32(f[j] - __uint_as_float(h[j]));
        }
        uint4* dst = reinterpret_cast<uint4*>(&aw[r * ROWW + kk * 8]);
        dst[0] = make_uint4(h[0], l[0], h[1], l[1]);
        dst[1] = make_uint4(h[2], l[2], h[3], l[3]);
    }
    __syncthreads();

    float4 acc[2][4];
#pragma unroll
    for (int mt = 0; mt < 2; mt++)
#pragma unroll
        for (int nt = 0; nt < 4; nt++) acc[mt][nt] = make_float4(0.f, 0.f, 0.f, 0.f);

    const int mrow = warp_m * 32;
    const int ncol = warp_n * 32;
    const int lq = lane >> 2;
    const int lr = lane & 3;

#pragma unroll 4
    for (int kt = 0; kt < 16; kt++) {
        const int k0 = kt * 8;
        uint32_t ahi[2][4], alo[2][4];
#pragma unroll
        for (int mt = 0; mt < 2; mt++) {
            int rb = mrow + mt * 16 + lq;
            uint2 q0 = *reinterpret_cast<const uint2*>(&aw[rb * ROWW + (k0 + lr) * 2]);
            uint2 q1 = *reinterpret_cast<const uint2*>(&aw[(rb + 8) * ROWW + (k0 + lr) * 2]);
            uint2 q2 = *reinterpret_cast<const uint2*>(&aw[rb * ROWW + (k0 + lr + 4) * 2]);
            uint2 q3 = *reinterpret_cast<const uint2*>(&aw[(rb + 8) * ROWW + (k0 + lr + 4) * 2]);
            ahi[mt][0] = q0.x; alo[mt][0] = q0.y;
            ahi[mt][1] = q1.x; alo[mt][1] = q1.y;
            ahi[mt][2] = q2.x; alo[mt][2] = q2.y;
            ahi[mt][3] = q3.x; alo[mt][3] = q3.y;
        }
#pragma unroll
        for (int nt = 0; nt < 4; nt++) {
            int col = ncol + nt * 8 + lq;
            uint4 B = Wp[col * 64 + kt * 4 + lr];
            uint32_t bhi[2] = {B.x, B.y};
            uint32_t blo[2] = {B.z, B.w};
#pragma unroll
            for (int mt = 0; mt < 2; mt++) {
                mma_tf32(acc[mt][nt], alo[mt], bhi);
                mma_tf32(acc[mt][nt], ahi[mt], blo);
                mma_tf32(acc[mt][nt], ahi[mt], bhi);
            }
        }
    }

    // epilogue: store Y (fp16) + fused attention dots (fp32)
    float ps[2][2] = {{0.f, 0.f}, {0.f, 0.f}};
    float pd[2][2] = {{0.f, 0.f}, {0.f, 0.f}};
#pragma unroll
    for (int mt = 0; mt < 2; mt++) {
#pragma unroll
        for (int nt = 0; nt < 4; nt++) {
            float4 a = acc[mt][nt];
            int col = ncol + nt * 8 + lr * 2;
            int row = row0 + mrow + mt * 16 + lq;
            float s0 = att_src[col], s1 = att_src[col + 1];
            float d0 = att_dst[col], d1 = att_dst[col + 1];
            ps[mt][0] += a.x * s0 + a.y * s1;
            pd[mt][0] += a.x * d0 + a.y * d1;
            ps[mt][1] += a.z * s0 + a.w * s1;
            pd[mt][1] += a.z * d0 + a.w * d1;
            if (row < nrows)
                Yh[(size_t)row * 64 + (col >> 1)] = __floats2half2_rn(a.x, a.y);
            if (row + 8 < nrows)
                Yh[(size_t)(row + 8) * 64 + (col >> 1)] = __floats2half2_rn(a.z, a.w);
        }
#pragma unroll
        for (int half = 0; half < 2; half++) {
#pragma unroll
            for (int off = 1; off <= 2; off <<= 1) {
                ps[mt][half] += __shfl_xor_sync(0xffffffffu, ps[mt][half], off);
                pd[mt][half] += __shfl_xor_sync(0xffffffffu, pd[mt][half], off);
            }
            if (lr == 0) {
                reds[warp][mt * 16 + half * 8 + lq] = ps[mt][half];
                redd[warp][mt * 16 + half * 8 + lq] = pd[mt][half];
            }
        }
    }
    __syncthreads();
    if (tid < 128) {
        int r = tid & 63, h = tid >> 6;
        int grow = row0 + r;
        if (grow < nrows) {
            int wm = r >> 5, rl = r & 31;
            int wA = wm * 4 + 2 * h;
            a_s[grow * 2 + h] = reds[wA][rl] + reds[wA + 1][rl];
            a_d[grow * 2 + h] = redd[wA][rl] + redd[wA + 1][rl];
        }
    }
}

// -- GEMM1 tf32x3 (BN+ELU fused on X) + fused attdot (H=1, 64 cols) ----------
// Output Y stored fp16 — consumed only by the agg1 gather.
__global__ void gemm1_tf32_att_kernel(const float4* __restrict__ X4,
                                      const uint4* __restrict__ Wp,
                                      __half2* __restrict__ Yh, int nrows,
                                      const float4* __restrict__ sc4,
                                      const float4* __restrict__ sh4,
                                      const float* __restrict__ att_src,
                                      const float* __restrict__ att_dst,
                                      float* __restrict__ a_s,
                                      float* __restrict__ a_d) {
    extern __shared__ uint32_t aw[];                 // [64][ROWW]
    __shared__ float reds[8][16], redd[8][16];
    const int tid  = threadIdx.x;
    const int lane = tid & 31;
    const int warp = tid >> 5;
    const int warp_m = warp >> 1;                    // 0..3 -> rows 16*wm
    const int warp_n = warp & 1;                     // 0..1 -> cols 32*wn
    const int row0 = blockIdx.x * 64;

    // stage X with BN+ELU, tf32 hi/lo interleaved
    for (int i = tid; i < 64 * 32; i += 256) {
        int r = i >> 5, kk = i & 31;
        int row = row0 + r;
        float4 raw = (row < nrows) ? X4[(size_t)row * 32 + kk]
                                   : make_float4(0.f, 0.f, 0.f, 0.f);
        float4 sc = sc4[kk], sh = sh4[kk];
        float f[4];
        f[0] = raw.x * sc.x + sh.x;
        f[1] = raw.y * sc.y + sh.y;
        f[2] = raw.z * sc.z + sh.z;
        f[3] = raw.w * sc.w + sh.w;
        uint32_t h[4], l[4];
#pragma unroll
        for (int j = 0; j < 4; j++) {
            f[j] = f[j] > 0.f ? f[j] : expm1f(f[j]);
            h[j] = f2tf32(f[j]);
            l[j] = f2tf32(f[j] - __uint_as_float(h[j]));
        }
        uint4* dst = reinterpret_cast<uint4*>(&aw[r * ROWW + kk * 8]);
        dst[0] = make_uint4(h[0], l[0], h[1], l[1]);
        dst[1] = make_uint4(h[2], l[2], h[3], l[3]);
    }
    __syncthreads();

    float4 acc[4];
#pragma unroll
    for (int nt = 0; nt < 4; nt++) acc[nt] = make_float4(0.f, 0.f, 0.f, 0.f);

    const int mrow = warp_m * 16;
    const int ncol = warp_n * 32;
    const int lq = lane >> 2;
    const int lr = lane & 3;

#pragma unroll 4
    for (int kt = 0; kt < 16; kt++) {
        const int k0 = kt * 8;
        uint2 q0 = *reinterpret_cast<const uint2*>(&aw[(mrow + lq) * ROWW + (k0 + lr) * 2]);
        uint2 q1 = *reinterpret_cast<const uint2*>(&aw[(mrow + 8 + lq) * ROWW + (k0 + lr) * 2]);
        uint2 q2 = *reinterpret_cast<const uint2*>(&aw[(mrow + lq) * ROWW + (k0 + lr + 4) * 2]);
        uint2 q3 = *reinterpret_cast<const uint2*>(&aw[(mrow + 8 + lq) * ROWW + (k0 + lr + 4) * 2]);
        uint32_t ahi[4] = {q0.x, q1.x, q2.x, q3.x};
        uint32_t alo[4] = {q0.y, q1.y, q2.y, q3.y};
#pragma unroll
        for (int nt = 0; nt < 4; nt++) {
            int col = ncol + nt * 8 + lq;
            uint4 B = Wp[col * 64 + kt * 4 + lr];
            uint32_t bhi[2] = {B.x, B.y};
            uint32_t blo[2] = {B.z, B.w};
            mma_tf32(acc[nt], alo, bhi);
            mma_tf32(acc[nt], ahi, blo);
            mma_tf32(acc[nt], ahi, bhi);
        }
    }

    // epilogue
    float ps[2] = {0.f, 0.f}, pd[2] = {0.f, 0.f};
#pragma unroll
    for (int nt = 0; nt < 4; nt++) {
        float4 a = acc[nt];
        int col = ncol + nt * 8 + lr * 2;
        int row = row0 + mrow + lq;
        float s0 = att_src[col], s1 = att_src[col + 1];
        float d0 = att_dst[col], d1 = att_dst[col + 1];
        ps[0] += a.x * s0 + a.y * s1;
        pd[0] += a.x * d0 + a.y * d1;
        ps[1] += a.z * s0 + a.w * s1;
        pd[1] += a.z * d0 + a.w * d1;
        if (row < nrows)
            Yh[(size_t)row * 32 + (col >> 1)] = __floats2half2_rn(a.x, a.y);
        if (row + 8 < nrows)
            Yh[(size_t)(row + 8) * 32 + (col >> 1)] = __floats2half2_rn(a.z, a.w);
    }
#pragma unroll
    for (int half = 0; half < 2; half++) {
#pragma unroll
        for (int off = 1; off <= 2; off <<= 1) {
            ps[half] += __shfl_xor_sync(0xffffffffu, ps[half], off);
            pd[half] += __shfl_xor_sync(0xffffffffu, pd[half], off);
        }
        if (lr == 0) {
            reds[warp][half * 8 + lq] = ps[half];
            redd[warp][half * 8 + lq] = pd[half];
        }
    }
    __syncthreads();
    if (tid < 64) {
        int grow = row0 + tid;
        if (grow < nrows) {
            int wm = tid >> 4, rl = tid & 15;
            a_s[grow] = reds[wm * 2][rl] + reds[wm * 2 + 1][rl];
            a_d[grow] = redd[wm * 2][rl] + redd[wm * 2 + 1][rl];
        }
    }
}

// ------- layer0: fused segment softmax + fp16 gather-aggregate (warp/node) ---
__global__ void agg0_kernel(const int* __restrict__ rowptr,
                            const int* __restrict__ adj,
                            const float* __restrict__ a_s,
                            const float* __restrict__ a_d,
                            const uint2* __restrict__ h,     // fp16 x4 per lane
                            float4* __restrict__ out,
                            const float* __restrict__ bias) {
    int node = (blockIdx.x * blockDim.x + threadIdx.x) >> 5;
    int lane = threadIdx.x & 31;
    if (node >= Nn) return;
    const int beg = rowptr[node], end = rowptr[node + 1];
    const float ad0 = a_d[node * 2 + 0];
    const float ad1 = a_d[node * 2 + 1];

    float m0 = -1e30f, m1 = -1e30f;
    for (int j = beg + lane; j < end; j += 32) {
        int s = adj[j];
        m0 = fmaxf(m0, lrelu(a_s[s * 2 + 0] + ad0));
        m1 = fmaxf(m1, lrelu(a_s[s * 2 + 1] + ad1));
    }
#pragma unroll
    for (int off = 16; off > 0; off >>= 1) {
        m0 = fmaxf(m0, __shfl_xor_sync(0xffffffffu, m0, off));
        m1 = fmaxf(m1, __shfl_xor_sync(0xffffffffu, m1, off));
    }

    const bool hi = (lane >= 16);
    float den0 = 0.f, den1 = 0.f;
    float4 acc = make_float4(0.f, 0.f, 0.f, 0.f);
    int j = beg;
    for (; j + 1 < end; j += 2) {
        int s0 = adj[j], s1 = adj[j + 1];
        uint2 r0 = h[(size_t)s0 * 32 + lane];
        uint2 r1 = h[(size_t)s1 * 32 + lane];
        float e00 = __expf(lrelu(a_s[s0 * 2 + 0] + ad0) - m0);
        float e01 = __expf(lrelu(a_s[s0 * 2 + 1] + ad1) - m1);
        float e10 = __expf(lrelu(a_s[s1 * 2 + 0] + ad0) - m0);
        float e11 = __expf(lrelu(a_s[s1 * 2 + 1] + ad1) - m1);
        den0 += e00 + e10; den1 += e01 + e11;
        float sc0 = hi ? e01 : e00;
        float sc1 = hi ? e11 : e10;
        float2 v0a = __half22float2(*reinterpret_cast<__half2*>(&r0.x));
        float2 v0b = __half22float2(*reinterpret_cast<__half2*>(&r0.y));
        float2 v1a = __half22float2(*reinterpret_cast<__half2*>(&r1.x));
        float2 v1b = __half22float2(*reinterpret_cast<__half2*>(&r1.y));
        acc.x += v0a.x * sc0 + v1a.x * sc1;
        acc.y += v0a.y * sc0 + v1a.y * sc1;
        acc.z += v0b.x * sc0 + v1b.x * sc1;
        acc.w += v0b.y * sc0 + v1b.y * sc1;
    }
    if (j < end) {
        int s = adj[j];
        uint2 r0 = h[(size_t)s * 32 + lane];
        float ex0 = __expf(lrelu(a_s[s * 2 + 0] + ad0) - m0);
        float ex1 = __expf(lrelu(a_s[s * 2 + 1] + ad1) - m1);
        den0 += ex0; den1 += ex1;
        float sc = hi ? ex1 : ex0;
        float2 va = __half22float2(*reinterpret_cast<__half2*>(&r0.x));
        float2 vb = __half22float2(*reinterpret_cast<__half2*>(&r0.y));
        acc.x += va.x * sc; acc.y += va.y * sc;
        acc.z += vb.x * sc; acc.w += vb.y * sc;
    }
    float inv = 1.f / ((hi ? den1 : den0) + 1e-16f);
    int c = lane * 4;
    float4 b4 = *reinterpret_cast<const float4*>(bias + c);
    float4 o;
    o.x = acc.x * inv + b4.x;
    o.y = acc.y * inv + b4.y;
    o.z = acc.z * inv + b4.z;
    o.w = acc.w * inv + b4.w;
    out[(size_t)node * (C0 / 4) + lane] = o;
}

// ------- layer1: fused segment softmax + fp16 gather-aggregate ---------------
__global__ void agg1_kernel(const int* __restrict__ rowptr,
                            const int* __restrict__ adj,
                            const float* __restrict__ a_s,
                            const float* __restrict__ a_d,
                            const __half2* __restrict__ h,   // fp16 x2 per lane
                            float2* __restrict__ out,
                            const float* __restrict__ bias) {
    int node = (blockIdx.x * blockDim.x + threadIdx.x) >> 5;
    int lane = threadIdx.x & 31;
    if (node >= Nn) return;
    const int beg = rowptr[node], end = rowptr[node + 1];
    const float ad = a_d[node];

    float m = -1e30f;
    for (int j = beg + lane; j < end; j += 32) {
        int s = adj[j];
        m = fmaxf(m, lrelu(a_s[s] + ad));
    }
#pragma unroll
    for (int off = 16; off > 0; off >>= 1)
        m = fmaxf(m, __shfl_xor_sync(0xffffffffu, m, off));

    float den = 0.f;
    float2 acc = make_float2(0.f, 0.f);
    int j = beg;
    for (; j + 1 < end; j += 2) {
        int s0 = adj[j], s1 = adj[j + 1];
        float2 v0 = __half22float2(h[(size_t)s0 * 32 + lane]);
        float2 v1 = __half22float2(h[(size_t)s1 * 32 + lane]);
        float e0 = __expf(lrelu(a_s[s0] + ad) - m);
        float e1 = __expf(lrelu(a_s[s1] + ad) - m);
        den += e0 + e1;
        acc.x += v0.x * e0 + v1.x * e1;
        acc.y += v0.y * e0 + v1.y * e1;
    }
    if (j < end) {
        int s = adj[j];
        float2 v = __half22float2(h[(size_t)s * 32 + lane]);
        float ex = __expf(lrelu(a_s[s] + ad) - m);
        den += ex;
        acc.x += v.x * ex; acc.y += v.y * ex;
    }
    float inv = 1.f / (den + 1e-16f);
    int c = lane * 2;
    float2 o;
    o.x = acc.x * inv + bias[c + 0];
    o.y = acc.y * inv + bias[c + 1];
    out[(size_t)node * (OUTD / 2) + lane] = o;
}

// ---------------- BN partial statistics (deterministic) ----------------
__global__ void bnsum_kernel(const float* __restrict__ x,
                             float* __restrict__ bps, float* __restrict__ bpq) {
    int c = threadIdx.x;                         // blockDim.x == 128
    float lsum = 0.f, lsq = 0.f;
    for (int row = blockIdx.x; row < Nn; row += gridDim.x) {
        float v = x[(size_t)row * C0 + c];
        lsum += v;
        lsq  += v * v;
    }
    bps[blockIdx.x * C0 + c] = lsum;
    bpq[blockIdx.x * C0 + c] = lsq;
}

__global__ void bnred_kernel(const float* __restrict__ bps,
                             const float* __restrict__ bpq,
                             const float* __restrict__ gamma,
                             const float* __restrict__ beta,
                             float* __restrict__ bnscale,
                             float* __restrict__ bnshift) {
    int c = threadIdx.x;                         // one block of 128 threads
    float s = 0.f, q = 0.f;
    for (int b = 0; b < BN_BLOCKS; b++) {
        s += bps[b * C0 + c];
        q += bpq[b * C0 + c];
    }
    const float invN = 1.0f / (float)Nn;
    float mu  = s * invN;
    float var = q * invN - mu * mu;
    float sc  = gamma[c] * rsqrtf(var + BN_EPS);
    bnscale[c] = sc;
    bnshift[c] = beta[c] - mu * sc;
}

// ---------------- launch ----------------
extern "C" void kernel_launch(void* const* d_in, const int* in_sizes, int n_in,
                              void* d_out, int out_size) {
    const float* data  = (const float*)d_in[0];
    const int*   ei    = (const int*)d_in[1];     // int32 (JAX x64 disabled)
    const float* W0    = (const float*)d_in[2];
    const float* asrc0 = (const float*)d_in[3];
    const float* adst0 = (const float*)d_in[4];
    const float* bias0 = (const float*)d_in[5];
    const float* gam0  = (const float*)d_in[6];
    const float* bet0  = (const float*)d_in[7];
    const float* W1    = (const float*)d_in[8];
    const float* asrc1 = (const float*)d_in[9];
    const float* adst1 = (const float*)d_in[10];
    const float* bias1 = (const float*)d_in[11];
    float* out = (float*)d_out;

    void *ph0, *px1, *ph1, *pa0s, *pa0d, *pa1s, *pa1d;
    void *pbps, *pbpq, *pbnscale, *pbnshift, *pw0p, *pw1p;
    void *pdeg, *pcnt, *pincl, *prowptr, *padj, *pbsum;
    cudaGetSymbolAddress(&ph0,  g_h0);
    cudaGetSymbolAddress(&px1,  g_x1);
    cudaGetSymbolAddress(&ph1,  g_h1);
    cudaGetSymbolAddress(&pa0s, g_a0s);
    cudaGetSymbolAddress(&pa0d, g_a0d);
    cudaGetSymbolAddress(&pa1s, g_a1s);
    cudaGetSymbolAddress(&pa1d, g_a1d);
    cudaGetSymbolAddress(&pbps,     g_bps);
    cudaGetSymbolAddress(&pbpq,     g_bpq);
    cudaGetSymbolAddress(&pbnscale, g_bnscale);
    cudaGetSymbolAddress(&pbnshift, g_bnshift);
    cudaGetSymbolAddress(&pw0p,  g_w0pack);
    cudaGetSymbolAddress(&pw1p,  g_w1pack);
    cudaGetSymbolAddress(&pdeg,   g_deg);
    cudaGetSymbolAddress(&pcnt,   g_cnt);
    cudaGetSymbolAddress(&pincl,  g_incl);
    cudaGetSymbolAddress(&prowptr,g_rowptr);
    cudaGetSymbolAddress(&padj,   g_adj);
    cudaGetSymbolAddress(&pbsum,  g_bsum);

    cudaFuncSetAttribute(gemm0_tf32_att_kernel,
                         cudaFuncAttributeMaxDynamicSharedMemorySize, GEMM_SMEM);
    cudaFuncSetAttribute(gemm1_tf32_att_kernel,
                         cudaFuncAttributeMaxDynamicSharedMemorySize, GEMM_SMEM);

    // launch order keeps gemm0 as the 4th launch (ncu capture window)
    wsplit_kernel<<<48, 256>>>(W0, W1, (uint4*)pw0p, (uint4*)pw1p);         // 1
    zero2_kernel<<<128, 256>>>((int*)pdeg, (int*)pcnt, Nn);                 // 2
    deg_kernel<<<(ET + 255) / 256, 256>>>(ei, (int*)pdeg);                  // 3
    gemm0_tf32_att_kernel<<<(Nn + 63) / 64, 256, GEMM_SMEM>>>(              // 4
        (const float4*)data, (const uint4*)pw0p, (__half2*)ph0, Nn,
        asrc0, adst0, (float*)pa0s, (float*)pa0d);
    scan1_kernel<<<NB1, SCAN_B>>>((int*)pdeg, (int*)pincl, (int*)pbsum);    // 5
    scan3_kernel<<<(Nn + 255) / 256, 256>>>((int*)pincl, (int*)pbsum,       // 6
                                            (int*)prowptr);
    fill_kernel<<<(ET + 255) / 256, 256>>>(ei, (int*)prowptr, (int*)pcnt,   // 7
                                           (int*)padj);
    agg0_kernel<<<(Nn + 7) / 8, 256>>>((int*)prowptr, (int*)padj,           // 8
                                       (float*)pa0s, (float*)pa0d,
                                       (const uint2*)ph0, (float4*)px1, bias0);
    bnsum_kernel<<<BN_BLOCKS, C0>>>((float*)px1, (float*)pbps, (float*)pbpq); // 9
    bnred_kernel<<<1, C0>>>((float*)pbps, (float*)pbpq, gam0, bet0,         // 10
                            (float*)pbnscale, (float*)pbnshift);
    gemm1_tf32_att_kernel<<<(Nn + 63) / 64, 256, GEMM_SMEM>>>(              // 11
        (const float4*)px1, (const uint4*)pw1p, (__half2*)ph1, Nn,
        (const float4*)pbnscale, (const float4*)pbnshift,
        asrc1, adst1, (float*)pa1s, (float*)pa1d);
    agg1_kernel<<<(Nn + 7) / 8, 256>>>((int*)prowptr, (int*)padj,           // 12
                                       (float*)pa1s, (float*)pa1d,
                                       (const __half2*)ph1, (float2*)out, bias1);
}